// round 2
// baseline (speedup 1.0000x reference)
#include <cuda_runtime.h>
#include <math.h>

#define BATCH 8
#define CDIM 256
#define NDIM 16384
#define HEADS 4
#define HD 64
#define NSPLIT 32
#define KSPLIT 512            // NDIM / NSPLIT
#define ATT_SCALE 0.125f      // 1/sqrt(64)
#define LDT 68                // padded ld for 64-wide tiles

// ---------------- scratch (static device memory; no allocation) ----------------
__device__ float g_Gpart[NSPLIT][BATCH][CDIM][CDIM]; // 64 MB
__device__ float g_rpart[NSPLIT][BATCH][CDIM];
__device__ float g_G[BATCH][CDIM][CDIM];
__device__ float g_r[BATCH][CDIM];
__device__ float g_T1[BATCH][HEADS][HD][CDIM];
__device__ float g_P[BATCH][HEADS][HD][HD];
__device__ float g_U[BATCH][CDIM][CDIM];
__device__ float g_u0[BATCH][CDIM];
__device__ float g_M[BATCH][CDIM][CDIM];
__device__ float g_cb[BATCH][CDIM];

// ---------------- 64x64-tile helpers (256 threads) ----------------
// dst[k][row] = src[row*ld + k]  (transposed into smem)
__device__ __forceinline__ void load_tile_T(float* dst, const float* __restrict__ src,
                                            int ld, int tid) {
#pragma unroll
    for (int l = 0; l < 4; l++) {
        int idx = tid + l * 256;
        int row = idx >> 4;
        int kq  = (idx & 15) << 2;
        float4 v = *(const float4*)(src + (size_t)row * ld + kq);
        dst[(kq + 0) * LDT + row] = v.x;
        dst[(kq + 1) * LDT + row] = v.y;
        dst[(kq + 2) * LDT + row] = v.z;
        dst[(kq + 3) * LDT + row] = v.w;
    }
}
// dst[row][c] = src[row*ld + c]
__device__ __forceinline__ void load_tile_N(float* dst, const float* __restrict__ src,
                                            int ld, int tid) {
#pragma unroll
    for (int l = 0; l < 4; l++) {
        int idx = tid + l * 256;
        int row = idx >> 4;
        int cq  = (idx & 15) << 2;
        *(float4*)(dst + row * LDT + cq) = *(const float4*)(src + (size_t)row * ld + cq);
    }
}
// acc[i][j] += sum_{k=0..63} sA[k][ty*4+i] * sB[k][tx*4+j]
__device__ __forceinline__ void mm64_step(const float* sA, const float* sB,
                                          float acc[4][4], int ty, int tx) {
#pragma unroll 16
    for (int kk = 0; kk < 64; kk++) {
        float4 a = *(const float4*)(sA + kk * LDT + ty * 4);
        float4 b = *(const float4*)(sB + kk * LDT + tx * 4);
        float av[4] = {a.x, a.y, a.z, a.w};
        float bv[4] = {b.x, b.y, b.z, b.w};
#pragma unroll
        for (int i = 0; i < 4; i++)
#pragma unroll
            for (int j = 0; j < 4; j++)
                acc[i][j] += av[i] * bv[j];
    }
}

// ================= K1: split-K Gram partials  Gpart = Xs * Xs^T =================
// grid (3 tiles, NSPLIT, BATCH); tiles (0,0),(0,1),(1,1) of 2x2 128-blocking
__global__ __launch_bounds__(256) void k1_gpart(const float* __restrict__ x) {
    __shared__ float sA[16 * 132];
    __shared__ float sB[16 * 132];
    int tid = threadIdx.x;
    int tileid = blockIdx.x, s = blockIdx.y, b = blockIdx.z;
    int ti = (tileid == 2) ? 1 : 0;
    int tj = (tileid == 0) ? 0 : 1;
    int i0 = ti * 128, j0 = tj * 128;
    const float* Ab = x + ((size_t)b * CDIM + i0) * NDIM + (size_t)s * KSPLIT;
    const float* Bb = x + ((size_t)b * CDIM + j0) * NDIM + (size_t)s * KSPLIT;
    float acc[8][8];
#pragma unroll
    for (int i = 0; i < 8; i++)
#pragma unroll
        for (int j = 0; j < 8; j++) acc[i][j] = 0.f;
    int ty = tid >> 4, tx = tid & 15;

    for (int kt = 0; kt < KSPLIT / 16; kt++) {
#pragma unroll
        for (int l = 0; l < 2; l++) {
            int idx = tid + l * 256;
            int row = idx >> 2;
            int kq  = (idx & 3) << 2;
            float4 va = *(const float4*)(Ab + (size_t)row * NDIM + kt * 16 + kq);
            sA[(kq + 0) * 132 + row] = va.x; sA[(kq + 1) * 132 + row] = va.y;
            sA[(kq + 2) * 132 + row] = va.z; sA[(kq + 3) * 132 + row] = va.w;
            float4 vb = *(const float4*)(Bb + (size_t)row * NDIM + kt * 16 + kq);
            sB[(kq + 0) * 132 + row] = vb.x; sB[(kq + 1) * 132 + row] = vb.y;
            sB[(kq + 2) * 132 + row] = vb.z; sB[(kq + 3) * 132 + row] = vb.w;
        }
        __syncthreads();
#pragma unroll
        for (int kk = 0; kk < 16; kk++) {
            float a[8], bb[8];
            *(float4*)(a)      = *(const float4*)(sA + kk * 132 + ty * 8);
            *(float4*)(a + 4)  = *(const float4*)(sA + kk * 132 + ty * 8 + 4);
            *(float4*)(bb)     = *(const float4*)(sB + kk * 132 + tx * 8);
            *(float4*)(bb + 4) = *(const float4*)(sB + kk * 132 + tx * 8 + 4);
#pragma unroll
            for (int i = 0; i < 8; i++)
#pragma unroll
                for (int j = 0; j < 8; j++) acc[i][j] += a[i] * bb[j];
        }
        __syncthreads();
    }
#pragma unroll
    for (int i = 0; i < 8; i++) {
        float* dst = &g_Gpart[s][b][i0 + ty * 8 + i][j0 + tx * 8];
        *(float4*)dst       = make_float4(acc[i][0], acc[i][1], acc[i][2], acc[i][3]);
        *(float4*)(dst + 4) = make_float4(acc[i][4], acc[i][5], acc[i][6], acc[i][7]);
    }
    // diagonal tiles also produce partial row-sums of x (for bias terms)
    if (ti == tj) {
        int warp = tid >> 5, lane = tid & 31;
        for (int rr = warp; rr < 128; rr += 8) {
            const float* rp = Ab + (size_t)rr * NDIM;
            float sum = 0.f;
            for (int c2 = lane; c2 < KSPLIT; c2 += 32) sum += rp[c2];
#pragma unroll
            for (int off = 16; off > 0; off >>= 1)
                sum += __shfl_down_sync(0xffffffffu, sum, off);
            if (lane == 0) g_rpart[s][b][i0 + rr] = sum;
        }
    }
}

// ================= K2: reduce split-K partials -> G, r =================
__global__ __launch_bounds__(256) void k2_reduce() {
    int i = blockIdx.x, b = blockIdx.y, j = threadIdx.x;
    float acc = 0.f;
    if (i >= 128 && j < 128) {   // tile (1,0) never written: read transpose of (0,1)
#pragma unroll 8
        for (int sp = 0; sp < NSPLIT; sp++) acc += g_Gpart[sp][b][j][i];
    } else {
#pragma unroll 8
        for (int sp = 0; sp < NSPLIT; sp++) acc += g_Gpart[sp][b][i][j];
    }
    g_G[b][i][j] = acc;
    if (j == 0) {
        float rs = 0.f;
        for (int sp = 0; sp < NSPLIT; sp++) rs += g_rpart[sp][b][i];
        g_r[b][i] = rs;
    }
}

// ================= K3: T1 = Wq_h @ G_b  (64 x 256 per (b,h)) =================
__global__ __launch_bounds__(256) void k3_t1(const float* __restrict__ Wqkv) {
    __shared__ float smem[2 * 64 * LDT];
    float* sA = smem;
    float* sB = smem + 64 * LDT;
    int cc = blockIdx.x, h = blockIdx.y, b = blockIdx.z;
    int tid = threadIdx.x;
    int ty = tid >> 4, tx = tid & 15;
    float acc[4][4];
#pragma unroll
    for (int i = 0; i < 4; i++)
#pragma unroll
        for (int j = 0; j < 4; j++) acc[i][j] = 0.f;
    for (int kc = 0; kc < 4; kc++) {
        load_tile_T(sA, Wqkv + (size_t)(h * HD) * CDIM + kc * 64, CDIM, tid); // sA[k][d]=Wq[d][k]
        load_tile_N(sB, &g_G[b][kc * 64][cc * 64], CDIM, tid);                // sB[k][c]
        __syncthreads();
        mm64_step(sA, sB, acc, ty, tx);
        __syncthreads();
    }
#pragma unroll
    for (int i = 0; i < 4; i++)
        *(float4*)&g_T1[b][h][ty * 4 + i][cc * 64 + tx * 4] =
            make_float4(acc[i][0], acc[i][1], acc[i][2], acc[i][3]);
}

// ======== K4: S = T1 @ Wk^T + bias rank-1 terms; softmax rows -> P, u0 ========
__global__ __launch_bounds__(256) void k4_attn(const float* __restrict__ Wqkv,
                                               const float* __restrict__ bqkv) {
    __shared__ float smem[2 * 64 * LDT];
    __shared__ float sr[CDIM];
    __shared__ float sqr[HD], srk[HD], sbq[HD], sbk[HD], sbv[HD];
    float* sA = smem;
    float* sB = smem + 64 * LDT;
    float* sS = smem;  // reused after GEMM (64*65 <= 2*64*LDT)
    int h = blockIdx.x, b = blockIdx.y;
    int tid = threadIdx.x;
    sr[tid] = g_r[b][tid];
    if (tid < HD)           sbq[tid]            = bqkv[h * HD + tid];
    else if (tid < 2 * HD)  sbk[tid - HD]       = bqkv[CDIM + h * HD + (tid - HD)];
    else if (tid < 3 * HD)  sbv[tid - 2 * HD]   = bqkv[2 * CDIM + h * HD + (tid - 2 * HD)];
    __syncthreads();
    if (tid < HD) {
        const float* wr = Wqkv + (size_t)(h * HD + tid) * CDIM;
        float q = 0.f;
        for (int i = 0; i < CDIM; i++) q += wr[i] * sr[i];
        sqr[tid] = q;                               // (Wq r)[d]
    } else if (tid < 2 * HD) {
        int e = tid - HD;
        const float* wr = Wqkv + (size_t)(CDIM + h * HD + e) * CDIM;
        float q = 0.f;
        for (int i = 0; i < CDIM; i++) q += wr[i] * sr[i];
        srk[e] = q;                                 // (Wk r)[e]
    }
    int ty = tid >> 4, tx = tid & 15;
    float acc[4][4];
#pragma unroll
    for (int i = 0; i < 4; i++)
#pragma unroll
        for (int j = 0; j < 4; j++) acc[i][j] = 0.f;
    for (int kc = 0; kc < 4; kc++) {
        load_tile_T(sA, &g_T1[b][h][0][kc * 64], CDIM, tid);                     // sA[c][d]
        load_tile_T(sB, Wqkv + (size_t)(CDIM + h * HD) * CDIM + kc * 64, CDIM, tid); // sB[c][e]
        __syncthreads();
        mm64_step(sA, sB, acc, ty, tx);
        __syncthreads();
    }
    float nf = (float)NDIM;
#pragma unroll
    for (int i = 0; i < 4; i++)
#pragma unroll
        for (int j = 0; j < 4; j++) {
            int d = ty * 4 + i, e = tx * 4 + j;
            float v = acc[i][j] + sbq[d] * srk[e] + sqr[d] * sbk[e] + nf * sbq[d] * sbk[e];
            sS[d * 65 + e] = v * ATT_SCALE;
        }
    __syncthreads();
    if (tid < HD) {
        int d = tid;
        float mx = -INFINITY;
        for (int e = 0; e < HD; e++) mx = fmaxf(mx, sS[d * 65 + e]);
        float sum = 0.f;
        for (int e = 0; e < HD; e++) {
            float ex = expf(sS[d * 65 + e] - mx);
            sS[d * 65 + e] = ex;
            sum += ex;
        }
        float inv = 1.f / sum;
        float pbv = 0.f;
        for (int e = 0; e < HD; e++) {
            float p = sS[d * 65 + e] * inv;
            g_P[b][h][d][e] = p;
            pbv += p * sbv[e];
        }
        g_u0[b][h * HD + d] = pbv;
    }
}

// ================= K5: U rows [h*64 .. ] = P_bh @ Wv_h  (64 x 256) =================
__global__ __launch_bounds__(256) void k5_u(const float* __restrict__ Wqkv) {
    __shared__ float smem[2 * 64 * LDT];
    float* sA = smem;
    float* sB = smem + 64 * LDT;
    int cc = blockIdx.x, h = blockIdx.y, b = blockIdx.z;
    int tid = threadIdx.x;
    int ty = tid >> 4, tx = tid & 15;
    float acc[4][4];
#pragma unroll
    for (int i = 0; i < 4; i++)
#pragma unroll
        for (int j = 0; j < 4; j++) acc[i][j] = 0.f;
    load_tile_T(sA, &g_P[b][h][0][0], 64, tid);                                    // sA[e][d]
    load_tile_N(sB, Wqkv + (size_t)(2 * CDIM + h * HD) * CDIM + cc * 64, CDIM, tid); // sB[e][c]
    __syncthreads();
    mm64_step(sA, sB, acc, ty, tx);
#pragma unroll
    for (int i = 0; i < 4; i++)
        *(float4*)&g_U[b][h * HD + ty * 4 + i][cc * 64 + tx * 4] =
            make_float4(acc[i][0], acc[i][1], acc[i][2], acc[i][3]);
}

// ================= K6: M_b = Wproj @ U_b =================
__global__ __launch_bounds__(256) void k6_m(const float* __restrict__ Wproj) {
    __shared__ float smem[2 * 64 * LDT];
    float* sA = smem;
    float* sB = smem + 64 * LDT;
    int cc = blockIdx.x, oc = blockIdx.y, b = blockIdx.z;
    int tid = threadIdx.x;
    int ty = tid >> 4, tx = tid & 15;
    float acc[4][4];
#pragma unroll
    for (int i = 0; i < 4; i++)
#pragma unroll
        for (int j = 0; j < 4; j++) acc[i][j] = 0.f;
    for (int kc = 0; kc < 4; kc++) {
        load_tile_T(sA, Wproj + (size_t)(oc * 64) * CDIM + kc * 64, CDIM, tid); // sA[m][o]
        load_tile_N(sB, &g_U[b][kc * 64][cc * 64], CDIM, tid);                  // sB[m][c]
        __syncthreads();
        mm64_step(sA, sB, acc, ty, tx);
        __syncthreads();
    }
#pragma unroll
    for (int i = 0; i < 4; i++)
        *(float4*)&g_M[b][oc * 64 + ty * 4 + i][cc * 64 + tx * 4] =
            make_float4(acc[i][0], acc[i][1], acc[i][2], acc[i][3]);
}

// ================= K6b: c_b = Wproj @ u0_b + bproj =================
__global__ __launch_bounds__(256) void k6b_c(const float* __restrict__ Wproj,
                                             const float* __restrict__ bproj) {
    __shared__ float su[CDIM];
    int b = blockIdx.x, o = threadIdx.x;
    su[o] = g_u0[b][o];
    __syncthreads();
    const float* wr = Wproj + (size_t)o * CDIM;
    float s = 0.f;
#pragma unroll 8
    for (int m = 0; m < CDIM; m++) s += wr[m] * su[m];
    g_cb[b][o] = s + bproj[o];
}

// ================= K7: out_b = M_b @ x_b + c_b 1^T =================
// grid (128 n-tiles, 2 row-tiles, 8 batches); 128x128 tile, 8x8 per thread
__global__ __launch_bounds__(256) void k7_out(const float* __restrict__ x,
                                              float* __restrict__ out) {
    __shared__ float sA[16 * 132];
    __shared__ float sB[16 * 132];
    __shared__ float sc[128];
    int tid = threadIdx.x;
    int nt = blockIdx.x, rt = blockIdx.y, b = blockIdx.z;
    int n0 = nt * 128, o0 = rt * 128;
    if (tid < 128) sc[tid] = g_cb[b][o0 + tid];
    const float* xb = x + (size_t)b * CDIM * NDIM;
    float acc[8][8];
#pragma unroll
    for (int i = 0; i < 8; i++)
#pragma unroll
        for (int j = 0; j < 8; j++) acc[i][j] = 0.f;
    int ty = tid >> 4, tx = tid & 15;

    for (int kt = 0; kt < CDIM / 16; kt++) {
        // sA[k][o] = M[o0+o][k0+k]  (transposed load)
#pragma unroll
        for (int l = 0; l < 2; l++) {
            int idx = tid + l * 256;
            int orow = idx >> 2;
            int kq   = (idx & 3) << 2;
            float4 v = *(const float4*)(&g_M[b][o0 + orow][kt * 16 + kq]);
            sA[(kq + 0) * 132 + orow] = v.x; sA[(kq + 1) * 132 + orow] = v.y;
            sA[(kq + 2) * 132 + orow] = v.z; sA[(kq + 3) * 132 + orow] = v.w;
        }
        // sB[k][n] = x[k0+k][n0+n]  (direct, coalesced)
#pragma unroll
        for (int l = 0; l < 2; l++) {
            int idx = tid + l * 256;
            int krow = idx >> 5;
            int nq   = (idx & 31) << 2;
            *(float4*)(sB + krow * 132 + nq) =
                *(const float4*)(xb + (size_t)(kt * 16 + krow) * NDIM + n0 + nq);
        }
        __syncthreads();
#pragma unroll
        for (int kk = 0; kk < 16; kk++) {
            float a[8], bb[8];
            *(float4*)(a)      = *(const float4*)(sA + kk * 132 + ty * 8);
            *(float4*)(a + 4)  = *(const float4*)(sA + kk * 132 + ty * 8 + 4);
            *(float4*)(bb)     = *(const float4*)(sB + kk * 132 + tx * 8);
            *(float4*)(bb + 4) = *(const float4*)(sB + kk * 132 + tx * 8 + 4);
#pragma unroll
            for (int i = 0; i < 8; i++)
#pragma unroll
                for (int j = 0; j < 8; j++) acc[i][j] += a[i] * bb[j];
        }
        __syncthreads();
    }
#pragma unroll
    for (int i = 0; i < 8; i++) {
        float cv = sc[ty * 8 + i];
        float* dst = out + ((size_t)b * CDIM + o0 + ty * 8 + i) * NDIM + n0 + tx * 8;
        *(float4*)dst       = make_float4(acc[i][0] + cv, acc[i][1] + cv,
                                          acc[i][2] + cv, acc[i][3] + cv);
        *(float4*)(dst + 4) = make_float4(acc[i][4] + cv, acc[i][5] + cv,
                                          acc[i][6] + cv, acc[i][7] + cv);
    }
}

extern "C" void kernel_launch(void* const* d_in, const int* in_sizes, int n_in,
                              void* d_out, int out_size) {
    const float* x     = (const float*)d_in[0];
    const float* Wqkv  = (const float*)d_in[1];
    const float* bqkv  = (const float*)d_in[2];
    const float* Wproj = (const float*)d_in[3];
    const float* bproj = (const float*)d_in[4];
    float* out = (float*)d_out;

    k1_gpart<<<dim3(3, NSPLIT, BATCH), 256>>>(x);
    k2_reduce<<<dim3(CDIM, BATCH), 256>>>();
    k3_t1<<<dim3(4, HEADS, BATCH), 256>>>(Wqkv);
    k4_attn<<<dim3(HEADS, BATCH), 256>>>(Wqkv, bqkv);
    k5_u<<<dim3(4, HEADS, BATCH), 256>>>(Wqkv);
    k6_m<<<dim3(4, 4, BATCH), 256>>>(Wproj);
    k6b_c<<<BATCH, 256>>>(Wproj, bproj);
    k7_out<<<dim3(NDIM / 128, 2, BATCH), 256>>>(x, out);
}